// round 14
// baseline (speedup 1.0000x reference)
#include <cuda_runtime.h>
#include <cstdint>

typedef unsigned long long u64;

#define GROUPS 8
#define CDIM 32
#define ROWS_PER_GROUP 262144
#define TOTAL_ROWS (GROUPS * ROWS_PER_GROUP)
#define EPSV 1e-5f
#define TITER 5

// ---- pass 1 config (R9 exact) ----
#define P1_BLOCKS_PER_GROUP 256
#define P1_GRID (GROUPS * P1_BLOCKS_PER_GROUP)   // 2048
#define P1_ROWS 1024
#define P1_WROWS 128
#define P1_CHUNK 16
#define P1_CHUNKS (P1_WROWS / P1_CHUNK)          // 8
#define ZR 36                                    // floats per staged sample row
#define WBUF_F (P1_CHUNK * ZR)                   // 576 floats = 2304 B per warp

// ---- reduction stage ----
#define RED_SLICES 32
#define RED_FOLD (P1_BLOCKS_PER_GROUP / RED_SLICES)

// ---- pass 2 config: row-paired accumulators ----
#define P2_TPB 128
#define P2_ROWS 256
#define P2_RP (P2_ROWS / 2)                      // 128 row-pairs
#define P2_GRID (TOTAL_ROWS / P2_ROWS)           // 8192
#define ZPST 33                                  // u64 stride per row-pair (gap after ch16)
#define MSPST 34                                 // u64 stride per Mt-splat row

// ---- scratch ----
__device__ __align__(16) float gCovPart[P1_GRID * 1024];
__device__ __align__(16) float gSumPart[P1_GRID * 32];
__device__ __align__(16) float gCov2[GROUPS * RED_SLICES * 1024];
__device__ __align__(16) float gSum2[GROUPS * RED_SLICES * 32];
__device__ __align__(16) float gMt[GROUPS * 1024];
__device__ __align__(16) float gBias[GROUPS * 32];

// ---- f32x2 helpers ----
__device__ __forceinline__ u64 pack2(float a, float b) {
    u64 r; asm("mov.b64 %0, {%1, %2};" : "=l"(r) : "f"(a), "f"(b)); return r;
}
__device__ __forceinline__ float2 unpack2(u64 v) {
    float2 r; asm("mov.b64 {%0, %1}, %2;" : "=f"(r.x), "=f"(r.y) : "l"(v)); return r;
}
__device__ __forceinline__ u64 ffma2(u64 a, u64 b, u64 c) {
    u64 d; asm("fma.rn.f32x2 %0, %1, %2, %3;" : "=l"(d) : "l"(a), "l"(b), "l"(c)); return d;
}

// ============================================================================
// Kernel 1: partial C = sum z z^T + channel sums (R9 exact, ~108us).
// ============================================================================
__global__ __launch_bounds__(256, 2) void k1_stats(const float4* __restrict__ in4) {
    __shared__ __align__(16) unsigned char smem_raw[32768];
    float* red = (float*)smem_raw;

    const int t   = threadIdx.x;
    const int bid = blockIdx.x;
    const int w   = t >> 5;
    const int l   = t & 31;
    const int h   = l >> 4;
    const int ti  = (l >> 2) & 3;
    const int tj  = l & 3;
    const int sl  = l & 7;

    float* wstf = (float*)(smem_raw + w * (WBUF_F * 4));

    u64 acc[8][4];
#pragma unroll
    for (int i = 0; i < 8; i++)
#pragma unroll
        for (int j = 0; j < 4; j++) acc[i][j] = 0ull;

    float msum[4] = {0.f, 0.f, 0.f, 0.f};

    const long wbase4 = (long)bid * (P1_ROWS * 8) + (long)w * (P1_WROWS * 8);

    float4 v[4];
#pragma unroll
    for (int kk = 0; kk < 4; kk++) v[kk] = in4[wbase4 + l + 32 * kk];

    for (int c = 0; c < P1_CHUNKS; c++) {
        __syncwarp();
#pragma unroll
        for (int kk = 0; kk < 4; kk++) {
            int f = l + 32 * kk;
            int s = f >> 3;
            msum[0] += v[kk].x; msum[1] += v[kk].y;
            msum[2] += v[kk].z; msum[3] += v[kk].w;
            *(float4*)(wstf + s * ZR + 4 * sl) = v[kk];
        }
        if (c + 1 < P1_CHUNKS) {
            long nb = wbase4 + (long)(c + 1) * (P1_CHUNK * 8);
#pragma unroll
            for (int kk = 0; kk < 4; kk++) v[kk] = in4[nb + l + 32 * kk];
        }
        __syncwarp();
#pragma unroll
        for (int ss = 0; ss < 8; ss++) {
            const float* row = wstf + (2 * ss + h) * ZR;
            float4 zia = *(const float4*)(row + 8 * ti);
            float4 zib = *(const float4*)(row + 8 * ti + 4);
            ulonglong2 zj0 = *(const ulonglong2*)(row + 8 * tj);
            ulonglong2 zj1 = *(const ulonglong2*)(row + 8 * tj + 4);
            u64 zj[4];
            zj[0] = zj0.x; zj[1] = zj0.y; zj[2] = zj1.x; zj[3] = zj1.y;
            u64 zi[8];
            zi[0] = pack2(zia.x, zia.x); zi[1] = pack2(zia.y, zia.y);
            zi[2] = pack2(zia.z, zia.z); zi[3] = pack2(zia.w, zia.w);
            zi[4] = pack2(zib.x, zib.x); zi[5] = pack2(zib.y, zib.y);
            zi[6] = pack2(zib.z, zib.z); zi[7] = pack2(zib.w, zib.w);
#pragma unroll
            for (int i = 0; i < 8; i++)
#pragma unroll
                for (int j = 0; j < 4; j++)
                    acc[i][j] = ffma2(zi[i], zj[j], acc[i][j]);
        }
    }
    __syncthreads();
#pragma unroll
    for (int i = 0; i < 8; i++)
#pragma unroll
        for (int j = 0; j < 4; j++) {
            float2 x = unpack2(acc[i][j]);
            float s0 = x.x + __shfl_xor_sync(0xffffffffu, x.x, 16);
            float s1 = x.y + __shfl_xor_sync(0xffffffffu, x.y, 16);
            if (h == 0) {
                red[w * 1024 + (8 * ti + i) * 32 + 8 * tj + 2 * j]     = s0;
                red[w * 1024 + (8 * ti + i) * 32 + 8 * tj + 2 * j + 1] = s1;
            }
        }
    __syncthreads();
#pragma unroll
    for (int r = 0; r < 4; r++) {
        int e = t + 256 * r;
        float s = 0.f;
#pragma unroll
        for (int ww = 0; ww < 8; ww++) s += red[ww * 1024 + e];
        gCovPart[(long)bid * 1024 + e] = s;
    }
    __syncthreads();
    red[t * 4 + 0] = msum[0]; red[t * 4 + 1] = msum[1];
    red[t * 4 + 2] = msum[2]; red[t * 4 + 3] = msum[3];
    __syncthreads();
    if (t < 32) {
        int kk = t >> 2, i = t & 3;
        float s = 0.f;
#pragma unroll 8
        for (int q = 0; q < 32; q++) s += red[(q * 8 + kk) * 4 + i];
        gSumPart[bid * 32 + t] = s;
    }
}

// ============================================================================
// Kernel 1b: fold 2048 partials -> 256  (R9 exact)
// ============================================================================
__global__ __launch_bounds__(256) void k_red() {
    const int t = threadIdx.x;
    const int bid = blockIdx.x;
    const long base = (long)bid * RED_FOLD;

#pragma unroll
    for (int r = 0; r < 4; r++) {
        int e = t + 256 * r;
        float s = 0.f;
#pragma unroll
        for (int f = 0; f < RED_FOLD; f++) s += gCovPart[(base + f) * 1024 + e];
        gCov2[(long)bid * 1024 + e] = s;
    }
    if (t < 32) {
        float s = 0.f;
#pragma unroll
        for (int f = 0; f < RED_FOLD; f++) s += gSumPart[(base + f) * 32 + t];
        gSum2[bid * 32 + t] = s;
    }
}

// ============================================================================
// Kernel 2: final reduce, build S, normalize, Newton-Schulz (R9 exact)
// ============================================================================
__global__ __launch_bounds__(1024) void k_solve() {
    __shared__ float S[1024], B[1024], T1[1024], T2[1024];
    __shared__ float mu[32];
    __shared__ float redw[32];
    __shared__ float normsh;

    const int t = threadIdx.x;
    const int g = blockIdx.x;
    const int i = t >> 5, j = t & 31;

    float cv = 0.f;
    const float* cp = gCov2 + (long)g * RED_SLICES * 1024;
#pragma unroll 8
    for (int bb = 0; bb < RED_SLICES; bb++) cv += cp[bb * 1024 + t];
    if (t < 32) {
        float s = 0.f;
        const float* sp = gSum2 + g * RED_SLICES * 32;
#pragma unroll 8
        for (int bb = 0; bb < RED_SLICES; bb++) s += sp[bb * 32 + t];
        mu[t] = s * (1.0f / (float)ROWS_PER_GROUP);
    }
    __syncthreads();

    float sij = cv - (float)ROWS_PER_GROUP * mu[i] * mu[j] + ((i == j) ? EPSV : 0.f);

    float v = sij * sij;
#pragma unroll
    for (int o = 16; o; o >>= 1) v += __shfl_xor_sync(0xffffffffu, v, o);
    if (j == 0) redw[i] = v;
    __syncthreads();
    if (t < 32) {
        float x = redw[t];
#pragma unroll
        for (int o = 16; o; o >>= 1) x += __shfl_xor_sync(0xffffffffu, x, o);
        if (t == 0) normsh = sqrtf(x);
    }
    __syncthreads();
    const float nrm = normsh;

    S[t] = sij / nrm;
    B[t] = (i == j) ? 1.f : 0.f;
    __syncthreads();

    for (int it = 0; it < TITER; it++) {
        float s1 = 0.f;
#pragma unroll
        for (int kk = 0; kk < 32; kk++) s1 += B[i * 32 + kk] * B[kk * 32 + j];
        T1[t] = s1; __syncthreads();
        float s2 = 0.f;
#pragma unroll
        for (int kk = 0; kk < 32; kk++) s2 += T1[i * 32 + kk] * B[kk * 32 + j];
        T2[t] = s2; __syncthreads();
        float s3 = 0.f;
#pragma unroll
        for (int kk = 0; kk < 32; kk++) s3 += T2[i * 32 + kk] * S[kk * 32 + j];
        float nb = 1.5f * B[t] - 0.5f * s3;
        __syncthreads();
        B[t] = nb;
        __syncthreads();
    }

    const float inv = rsqrtf(nrm);
    float mt = B[j * 32 + i] * inv;
    gMt[g * 1024 + t] = mt;
    T1[t] = mt;
    __syncthreads();
    if (t < 32) {
        float bsum = 0.f;
#pragma unroll
        for (int d = 0; d < 32; d++) bsum += mu[d] * T1[d * 32 + t];
        gBias[g * 32 + t] = -bsum;
    }
}

// ============================================================================
// Kernel 3: out[n] = z[n] @ Mt + bias. ROW-PAIRED f32x2:
// acc[rp][c] = (out[2rp][c], out[2rp+1][c]). Mt splatted ONCE per block into
// msp[d][c]=(Mt,Mt); z staged pre-paired zp[rp][c]=(z_even,z_odd). Hot loop:
// per d per thread: 4 uniform-ish LDS.128 (Mt) + 4 LDS.64 (z) -> 32 FFMA2,
// ZERO packs. Bytes/row: z 128 (was 512) + Mt 256 + LDG/STS/STG 384 = 768.
// Thread (m=t&3: channels 8m..8m+7; q=t>>2: row-pairs q+32*rr, rr<4).
// ============================================================================
__global__ __launch_bounds__(P2_TPB, 4) void k2_apply(const float4* __restrict__ in4,
                                                      float4* __restrict__ out4) {
    __shared__ u64 zp[P2_RP * ZPST];                 // 33792 B
    __shared__ __align__(16) u64 msp[32 * MSPST];    // 8704 B  Mt splat
    __shared__ u64 bsp[32];

    const int t = threadIdx.x;
    const int g = blockIdx.x >> 10;                  // 1024 blocks per group
    const long R0 = (long)blockIdx.x * P2_ROWS;

    // ---- build Mt splat (gap 2 u64 after ch16 -> distinct bank quads) ----
    const float* mtg = gMt + g * 1024;
#pragma unroll
    for (int i = 0; i < 8; i++) {
        int idx = t + 128 * i;
        int d = idx >> 5, c = idx & 31;
        float vv = mtg[idx];
        msp[d * MSPST + c + 2 * (c >> 4)] = pack2(vv, vv);
    }
    if (t < 32) { float b = gBias[g * 32 + t]; bsp[t] = pack2(b, b); }

    // ---- stage z pre-paired: lane (sp=t>>3, sk=t&7) loads rows 2rp,2rp+1 ----
    {
        const int sk = t & 7, sp = t >> 3;           // sp 0..15
#pragma unroll
        for (int i = 0; i < 8; i++) {
            int rp = sp + 16 * i;
            float4 va = in4[R0 * 8 + (2 * rp) * 8 + sk];
            float4 vb = in4[R0 * 8 + (2 * rp + 1) * 8 + sk];
            u64* dst = zp + rp * ZPST + 4 * sk + (sk >> 2);   // gap after ch16
            dst[0] = pack2(va.x, vb.x);
            dst[1] = pack2(va.y, vb.y);
            dst[2] = pack2(va.z, vb.z);
            dst[3] = pack2(va.w, vb.w);
        }
    }
    __syncthreads();

    const int m = t & 3;
    const int q = t >> 2;                            // 0..31
    const int mtoff = 8 * m + 2 * (m >> 1);          // msp in-row offset

    u64 acc[4][8];
#pragma unroll
    for (int rr = 0; rr < 4; rr++)
#pragma unroll
        for (int c = 0; c < 8; c++) acc[rr][c] = bsp[8 * m + c];

#pragma unroll 4
    for (int d = 0; d < 32; d++) {
        const u64* zcol = zp + d + (d >> 4);
        const ulonglong2* mrow = (const ulonglong2*)(msp + d * MSPST + mtoff);
        ulonglong2 m0 = mrow[0], m1 = mrow[1], m2 = mrow[2], m3 = mrow[3];
#pragma unroll
        for (int rr = 0; rr < 4; rr++) {
            u64 zz = zcol[(q + 32 * rr) * ZPST];
            acc[rr][0] = ffma2(zz, m0.x, acc[rr][0]);
            acc[rr][1] = ffma2(zz, m0.y, acc[rr][1]);
            acc[rr][2] = ffma2(zz, m1.x, acc[rr][2]);
            acc[rr][3] = ffma2(zz, m1.y, acc[rr][3]);
            acc[rr][4] = ffma2(zz, m2.x, acc[rr][4]);
            acc[rr][5] = ffma2(zz, m2.y, acc[rr][5]);
            acc[rr][6] = ffma2(zz, m3.x, acc[rr][6]);
            acc[rr][7] = ffma2(zz, m3.y, acc[rr][7]);
        }
    }

    // ---- epilogue: unpack (even,odd) rows, 4 STG.128 per row-pair ----
#pragma unroll
    for (int rr = 0; rr < 4; rr++) {
        int rp = q + 32 * rr;
        long re = (R0 + 2 * rp) * 8;                 // even row float4 base
        float2 c0 = unpack2(acc[rr][0]), c1 = unpack2(acc[rr][1]);
        float2 c2 = unpack2(acc[rr][2]), c3 = unpack2(acc[rr][3]);
        float2 c4 = unpack2(acc[rr][4]), c5 = unpack2(acc[rr][5]);
        float2 c6 = unpack2(acc[rr][6]), c7 = unpack2(acc[rr][7]);
        out4[re + 2 * m + 0]     = make_float4(c0.x, c1.x, c2.x, c3.x);
        out4[re + 2 * m + 1]     = make_float4(c4.x, c5.x, c6.x, c7.x);
        out4[re + 8 + 2 * m + 0] = make_float4(c0.y, c1.y, c2.y, c3.y);
        out4[re + 8 + 2 * m + 1] = make_float4(c4.y, c5.y, c6.y, c7.y);
    }
}

// ============================================================================
extern "C" void kernel_launch(void* const* d_in, const int* in_sizes, int n_in,
                              void* d_out, int out_size) {
    const float4* in4 = (const float4*)d_in[0];
    float4* out4 = (float4*)d_out;

    k1_stats<<<P1_GRID, 256>>>(in4);
    k_red<<<GROUPS * RED_SLICES, 256>>>();
    k_solve<<<GROUPS, 1024>>>();
    k2_apply<<<P2_GRID, P2_TPB>>>(in4, out4);
}

// round 15
// speedup vs baseline: 1.0058x; 1.0058x over previous
#include <cuda_runtime.h>
#include <cstdint>

typedef unsigned long long u64;

#define GROUPS 8
#define CDIM 32
#define ROWS_PER_GROUP 262144
#define TOTAL_ROWS (GROUPS * ROWS_PER_GROUP)
#define EPSV 1e-5f
#define TITER 5

// ---- pass 1 config (R9 + depth-2 prefetch) ----
#define P1_BLOCKS_PER_GROUP 256
#define P1_GRID (GROUPS * P1_BLOCKS_PER_GROUP)   // 2048
#define P1_ROWS 1024
#define P1_WROWS 128
#define P1_CHUNK 16
#define P1_CHUNKS (P1_WROWS / P1_CHUNK)          // 8
#define ZR 36                                    // floats per staged sample row
#define WBUF_F (P1_CHUNK * ZR)                   // 576 floats = 2304 B per warp

// ---- reduction stage ----
#define RED_SLICES 32
#define RED_FOLD (P1_BLOCKS_PER_GROUP / RED_SLICES)

// ---- pass 2 config (R9 exact) ----
#define P2_TPB 128
#define P2_ROWS 256
#define P2_GRID (TOTAL_ROWS / P2_ROWS)           // 8192
#define ZST 34

// ---- scratch ----
__device__ __align__(16) float gCovPart[P1_GRID * 1024];
__device__ __align__(16) float gSumPart[P1_GRID * 32];
__device__ __align__(16) float gCov2[GROUPS * RED_SLICES * 1024];
__device__ __align__(16) float gSum2[GROUPS * RED_SLICES * 32];
__device__ __align__(16) float gMt[GROUPS * 1024];
__device__ __align__(16) float gBias[GROUPS * 32];

// ---- f32x2 helpers ----
__device__ __forceinline__ u64 pack2(float a, float b) {
    u64 r; asm("mov.b64 %0, {%1, %2};" : "=l"(r) : "f"(a), "f"(b)); return r;
}
__device__ __forceinline__ float2 unpack2(u64 v) {
    float2 r; asm("mov.b64 {%0, %1}, %2;" : "=f"(r.x), "=f"(r.y) : "l"(v)); return r;
}
__device__ __forceinline__ u64 ffma2(u64 a, u64 b, u64 c) {
    u64 d; asm("fma.rn.f32x2 %0, %1, %2, %3;" : "=l"(d) : "l"(a), "l"(b), "l"(c)); return d;
}

// ============================================================================
// Kernel 1: partial C = sum z z^T + channel sums. R9 body with DEPTH-2 LDG
// prefetch: LDG for chunk c+2 issues when chunk c stages (~700 cyc cover vs
// 577 cyc DRAM latency; depth-1 only covered ~300 cyc -> exposed stalls).
// v[2][4] double prefetch regs (+16), acc[8][4]=64 -> ~115 regs, 2 blocks/SM.
// ============================================================================
__global__ __launch_bounds__(256, 2) void k1_stats(const float4* __restrict__ in4) {
    __shared__ __align__(16) unsigned char smem_raw[32768];
    float* red = (float*)smem_raw;

    const int t   = threadIdx.x;
    const int bid = blockIdx.x;
    const int w   = t >> 5;
    const int l   = t & 31;
    const int h   = l >> 4;         // half: even/odd samples
    const int ti  = (l >> 2) & 3;   // i channels 8ti..8ti+7
    const int tj  = l & 3;          // j channels 8tj..8tj+7
    const int sl  = l & 7;          // staging slot (channels 4sl..4sl+3)

    float* wstf = (float*)(smem_raw + w * (WBUF_F * 4));

    u64 acc[8][4];
#pragma unroll
    for (int i = 0; i < 8; i++)
#pragma unroll
        for (int j = 0; j < 4; j++) acc[i][j] = 0ull;

    float msum[4] = {0.f, 0.f, 0.f, 0.f};

    const long wbase4 = (long)bid * (P1_ROWS * 8) + (long)w * (P1_WROWS * 8);

    // depth-2 prefetch: vq[0] holds chunk 0, vq[1] holds chunk 1
    float4 vq[2][4];
#pragma unroll
    for (int kk = 0; kk < 4; kk++) vq[0][kk] = in4[wbase4 + l + 32 * kk];
#pragma unroll
    for (int kk = 0; kk < 4; kk++) vq[1][kk] = in4[wbase4 + (P1_CHUNK * 8) + l + 32 * kk];

    for (int c = 0; c < P1_CHUNKS; c++) {
        const int p = c & 1;
        __syncwarp();   // prior chunk's reads done before overwrite
        // ---- stage chunk c from vq[p] + channel sums ----
#pragma unroll
        for (int kk = 0; kk < 4; kk++) {
            int f = l + 32 * kk;
            int s = f >> 3;
            msum[0] += vq[p][kk].x; msum[1] += vq[p][kk].y;
            msum[2] += vq[p][kk].z; msum[3] += vq[p][kk].w;
            *(float4*)(wstf + s * ZR + 4 * sl) = vq[p][kk];
        }
        // ---- prefetch chunk c+2 into vq[p] (frees as it stages) ----
        if (c + 2 < P1_CHUNKS) {
            long nb = wbase4 + (long)(c + 2) * (P1_CHUNK * 8);
#pragma unroll
            for (int kk = 0; kk < 4; kk++) vq[p][kk] = in4[nb + l + 32 * kk];
        }
        __syncwarp();   // stores visible
        // ---- compute: half h processes samples 2ss+h ----
#pragma unroll
        for (int ss = 0; ss < 8; ss++) {
            const float* row = wstf + (2 * ss + h) * ZR;
            float4 zia = *(const float4*)(row + 8 * ti);
            float4 zib = *(const float4*)(row + 8 * ti + 4);
            ulonglong2 zj0 = *(const ulonglong2*)(row + 8 * tj);
            ulonglong2 zj1 = *(const ulonglong2*)(row + 8 * tj + 4);
            u64 zj[4];
            zj[0] = zj0.x; zj[1] = zj0.y; zj[2] = zj1.x; zj[3] = zj1.y;
            u64 zi[8];
            zi[0] = pack2(zia.x, zia.x); zi[1] = pack2(zia.y, zia.y);
            zi[2] = pack2(zia.z, zia.z); zi[3] = pack2(zia.w, zia.w);
            zi[4] = pack2(zib.x, zib.x); zi[5] = pack2(zib.y, zib.y);
            zi[6] = pack2(zib.z, zib.z); zi[7] = pack2(zib.w, zib.w);
#pragma unroll
            for (int i = 0; i < 8; i++)
#pragma unroll
                for (int j = 0; j < 4; j++)
                    acc[i][j] = ffma2(zi[i], zj[j], acc[i][j]);
        }
    }
    __syncthreads();
#pragma unroll
    for (int i = 0; i < 8; i++)
#pragma unroll
        for (int j = 0; j < 4; j++) {
            float2 x = unpack2(acc[i][j]);
            float s0 = x.x + __shfl_xor_sync(0xffffffffu, x.x, 16);
            float s1 = x.y + __shfl_xor_sync(0xffffffffu, x.y, 16);
            if (h == 0) {
                red[w * 1024 + (8 * ti + i) * 32 + 8 * tj + 2 * j]     = s0;
                red[w * 1024 + (8 * ti + i) * 32 + 8 * tj + 2 * j + 1] = s1;
            }
        }
    __syncthreads();
#pragma unroll
    for (int r = 0; r < 4; r++) {
        int e = t + 256 * r;
        float s = 0.f;
#pragma unroll
        for (int ww = 0; ww < 8; ww++) s += red[ww * 1024 + e];
        gCovPart[(long)bid * 1024 + e] = s;
    }
    __syncthreads();
    red[t * 4 + 0] = msum[0]; red[t * 4 + 1] = msum[1];
    red[t * 4 + 2] = msum[2]; red[t * 4 + 3] = msum[3];
    __syncthreads();
    if (t < 32) {
        int kk = t >> 2, i = t & 3;
        float s = 0.f;
#pragma unroll 8
        for (int q = 0; q < 32; q++) s += red[(q * 8 + kk) * 4 + i];
        gSumPart[bid * 32 + t] = s;
    }
}

// ============================================================================
// Kernel 1b: fold 2048 partials -> 256  (R9 exact)
// ============================================================================
__global__ __launch_bounds__(256) void k_red() {
    const int t = threadIdx.x;
    const int bid = blockIdx.x;
    const long base = (long)bid * RED_FOLD;

#pragma unroll
    for (int r = 0; r < 4; r++) {
        int e = t + 256 * r;
        float s = 0.f;
#pragma unroll
        for (int f = 0; f < RED_FOLD; f++) s += gCovPart[(base + f) * 1024 + e];
        gCov2[(long)bid * 1024 + e] = s;
    }
    if (t < 32) {
        float s = 0.f;
#pragma unroll
        for (int f = 0; f < RED_FOLD; f++) s += gSumPart[(base + f) * 32 + t];
        gSum2[bid * 32 + t] = s;
    }
}

// ============================================================================
// Kernel 2: final reduce, build S, normalize, Newton-Schulz (R9 exact)
// ============================================================================
__global__ __launch_bounds__(1024) void k_solve() {
    __shared__ float S[1024], B[1024], T1[1024], T2[1024];
    __shared__ float mu[32];
    __shared__ float redw[32];
    __shared__ float normsh;

    const int t = threadIdx.x;
    const int g = blockIdx.x;
    const int i = t >> 5, j = t & 31;

    float cv = 0.f;
    const float* cp = gCov2 + (long)g * RED_SLICES * 1024;
#pragma unroll 8
    for (int bb = 0; bb < RED_SLICES; bb++) cv += cp[bb * 1024 + t];
    if (t < 32) {
        float s = 0.f;
        const float* sp = gSum2 + g * RED_SLICES * 32;
#pragma unroll 8
        for (int bb = 0; bb < RED_SLICES; bb++) s += sp[bb * 32 + t];
        mu[t] = s * (1.0f / (float)ROWS_PER_GROUP);
    }
    __syncthreads();

    float sij = cv - (float)ROWS_PER_GROUP * mu[i] * mu[j] + ((i == j) ? EPSV : 0.f);

    float v = sij * sij;
#pragma unroll
    for (int o = 16; o; o >>= 1) v += __shfl_xor_sync(0xffffffffu, v, o);
    if (j == 0) redw[i] = v;
    __syncthreads();
    if (t < 32) {
        float x = redw[t];
#pragma unroll
        for (int o = 16; o; o >>= 1) x += __shfl_xor_sync(0xffffffffu, x, o);
        if (t == 0) normsh = sqrtf(x);
    }
    __syncthreads();
    const float nrm = normsh;

    S[t] = sij / nrm;
    B[t] = (i == j) ? 1.f : 0.f;
    __syncthreads();

    for (int it = 0; it < TITER; it++) {
        float s1 = 0.f;
#pragma unroll
        for (int kk = 0; kk < 32; kk++) s1 += B[i * 32 + kk] * B[kk * 32 + j];
        T1[t] = s1; __syncthreads();
        float s2 = 0.f;
#pragma unroll
        for (int kk = 0; kk < 32; kk++) s2 += T1[i * 32 + kk] * B[kk * 32 + j];
        T2[t] = s2; __syncthreads();
        float s3 = 0.f;
#pragma unroll
        for (int kk = 0; kk < 32; kk++) s3 += T2[i * 32 + kk] * S[kk * 32 + j];
        float nb = 1.5f * B[t] - 0.5f * s3;
        __syncthreads();
        B[t] = nb;
        __syncthreads();
    }

    const float inv = rsqrtf(nrm);
    float mt = B[j * 32 + i] * inv;
    gMt[g * 1024 + t] = mt;
    T1[t] = mt;
    __syncthreads();
    if (t < 32) {
        float bsum = 0.f;
#pragma unroll
        for (int d = 0; d < 32; d++) bsum += mu[d] * T1[d * 32 + t];
        gBias[g * 32 + t] = -bsum;
    }
}

// ============================================================================
// Kernel 3: out[n] = z[n] @ Mt + bias. R9 exact (measured 103.5us).
// ============================================================================
__global__ __launch_bounds__(P2_TPB, 3) void k2_apply(const float4* __restrict__ in4,
                                                      float4* __restrict__ out4) {
    __shared__ __align__(16) float zbuf[P2_ROWS * ZST];  // 34816 B
    __shared__ __align__(16) u64 mt2[512];
    __shared__ u64 bias2[16];

    const int t = threadIdx.x;
    const int g = blockIdx.x >> 10;          // 1024 blocks per group

    const u64* mtg = (const u64*)gMt + g * 512;
#pragma unroll
    for (int i = 0; i < 4; i++) mt2[t + 128 * i] = mtg[t + 128 * i];
    if (t < 16) bias2[t] = ((const u64*)gBias)[g * 16 + t];

    const int m = t & 3;
    const int q = t >> 2;                    // 0..31
    const long R0 = (long)blockIdx.x * P2_ROWS;

    // ---- stage 256 rows: coalesced LDG.128, float2 smem stores ----
#pragma unroll
    for (int i = 0; i < 16; i++) {
        int f = t + 128 * i;                 // float4 id in tile
        int row = f >> 3, sl = f & 7;
        float4 v = in4[R0 * 8 + f];
        float2* d = (float2*)(zbuf + row * ZST + 4 * sl);
        d[0] = make_float2(v.x, v.y);
        d[1] = make_float2(v.z, v.w);
    }
    __syncthreads();

    u64 acc[8][4];
#pragma unroll
    for (int rr = 0; rr < 8; rr++)
#pragma unroll
        for (int jj = 0; jj < 4; jj++) acc[rr][jj] = bias2[m * 4 + jj];

    const ulonglong2* mtv = (const ulonglong2*)mt2;
#pragma unroll 4
    for (int dp = 0; dp < 16; dp++) {
        const int d0 = 2 * dp;
        ulonglong2 ma0 = mtv[d0 * 8 + m * 2 + 0];
        ulonglong2 mb0 = mtv[d0 * 8 + m * 2 + 1];
        ulonglong2 ma1 = mtv[d0 * 8 + m * 2 + 8];   // (d0+1)
        ulonglong2 mb1 = mtv[d0 * 8 + m * 2 + 9];
#pragma unroll
        for (int rr = 0; rr < 8; rr++) {
            float2 z2 = *(const float2*)(zbuf + (q + 32 * rr) * ZST + d0);
            u64 zz0 = pack2(z2.x, z2.x);
            u64 zz1 = pack2(z2.y, z2.y);
            acc[rr][0] = ffma2(zz0, ma0.x, acc[rr][0]);
            acc[rr][1] = ffma2(zz0, ma0.y, acc[rr][1]);
            acc[rr][2] = ffma2(zz0, mb0.x, acc[rr][2]);
            acc[rr][3] = ffma2(zz0, mb0.y, acc[rr][3]);
            acc[rr][0] = ffma2(zz1, ma1.x, acc[rr][0]);
            acc[rr][1] = ffma2(zz1, ma1.y, acc[rr][1]);
            acc[rr][2] = ffma2(zz1, mb1.x, acc[rr][2]);
            acc[rr][3] = ffma2(zz1, mb1.y, acc[rr][3]);
        }
    }

#pragma unroll
    for (int rr = 0; rr < 8; rr++) {
        float2 p0 = unpack2(acc[rr][0]), p1 = unpack2(acc[rr][1]);
        float2 p2 = unpack2(acc[rr][2]), p3 = unpack2(acc[rr][3]);
        long rowb = (R0 + q + 32 * rr) * 8;
        out4[rowb + m * 2 + 0] = make_float4(p0.x, p0.y, p1.x, p1.y);
        out4[rowb + m * 2 + 1] = make_float4(p2.x, p2.y, p3.x, p3.y);
    }
}

// ============================================================================
extern "C" void kernel_launch(void* const* d_in, const int* in_sizes, int n_in,
                              void* d_out, int out_size) {
    const float4* in4 = (const float4*)d_in[0];
    float4* out4 = (float4*)d_out;

    k1_stats<<<P1_GRID, 256>>>(in4);
    k_red<<<GROUPS * RED_SLICES, 256>>>();
    k_solve<<<GROUPS, 1024>>>();
    k2_apply<<<P2_GRID, P2_TPB>>>(in4, out4);
}

// round 16
// speedup vs baseline: 1.1651x; 1.1584x over previous
#include <cuda_runtime.h>
#include <cstdint>

typedef unsigned long long u64;

#define GROUPS 8
#define CDIM 32
#define ROWS_PER_GROUP 262144
#define TOTAL_ROWS (GROUPS * ROWS_PER_GROUP)
#define EPSV 1e-5f
#define TITER 5

// ---- pass 1 config: cp.async staging, 2 per-warp buffers ----
#define P1_BLOCKS_PER_GROUP 256
#define P1_GRID (GROUPS * P1_BLOCKS_PER_GROUP)   // 2048
#define P1_ROWS 1024
#define P1_WROWS 128
#define P1_CHUNK 16
#define P1_CHUNKS (P1_WROWS / P1_CHUNK)          // 8
#define ZR 36                                    // floats per staged sample row
#define BUF_B (P1_CHUNK * ZR * 4)                // 2304 B per buffer
#define WARP_B (2 * BUF_B)                       // 4608 B per warp (double buffer)
// smem: 8 warps * 4608 = 36864 B; union with red (32768 B) -> 36864 static

// ---- reduction stage ----
#define RED_SLICES 32
#define RED_FOLD (P1_BLOCKS_PER_GROUP / RED_SLICES)

// ---- pass 2 config (R9 exact) ----
#define P2_TPB 128
#define P2_ROWS 256
#define P2_GRID (TOTAL_ROWS / P2_ROWS)           // 8192
#define ZST 34

// ---- scratch ----
__device__ __align__(16) float gCovPart[P1_GRID * 1024];
__device__ __align__(16) float gSumPart[P1_GRID * 32];
__device__ __align__(16) float gCov2[GROUPS * RED_SLICES * 1024];
__device__ __align__(16) float gSum2[GROUPS * RED_SLICES * 32];
__device__ __align__(16) float gMt[GROUPS * 1024];
__device__ __align__(16) float gBias[GROUPS * 32];

// ---- f32x2 helpers ----
__device__ __forceinline__ u64 pack2(float a, float b) {
    u64 r; asm("mov.b64 %0, {%1, %2};" : "=l"(r) : "f"(a), "f"(b)); return r;
}
__device__ __forceinline__ float2 unpack2(u64 v) {
    float2 r; asm("mov.b64 {%0, %1}, %2;" : "=f"(r.x), "=f"(r.y) : "l"(v)); return r;
}
__device__ __forceinline__ u64 ffma2(u64 a, u64 b, u64 c) {
    u64 d; asm("fma.rn.f32x2 %0, %1, %2, %3;" : "=l"(d) : "l"(a), "l"(b), "l"(c)); return d;
}

// ---- cp.async helpers ----
__device__ __forceinline__ void cp16(uint32_t dst_smem, const void* src) {
    asm volatile("cp.async.cg.shared.global [%0], [%1], 16;"
                 :: "r"(dst_smem), "l"(src) : "memory");
}
__device__ __forceinline__ void cp_commit() {
    asm volatile("cp.async.commit_group;" ::: "memory");
}
template <int N>
__device__ __forceinline__ void cp_wait() {
    asm volatile("cp.async.wait_group %0;" :: "n"(N) : "memory");
}

// ============================================================================
// Kernel 1: partial C = sum z z^T + channel sums. R9 compute body, staging
// via cp.async (.cg, 16B) into 2 per-warp smem buffers: NO prefetch/staging
// registers, no STS, L1 load path bypassed. Pipeline: preload chunks 0,1;
// loop c: wait_group -> syncwarp -> compute c (+msum column pass) ->
// syncwarp -> issue chunk c+2 into buf[c&1] -> commit.
// Lane l: half h=l>>4, tile ti=(l>>2)&3, tj=l&3; acc[8][4]=64 regs.
// ============================================================================
__global__ __launch_bounds__(256, 2) void k1_stats(const float4* __restrict__ in4) {
    __shared__ __align__(16) unsigned char smem_raw[36864];
    float* red = (float*)smem_raw;

    const int t   = threadIdx.x;
    const int bid = blockIdx.x;
    const int w   = t >> 5;
    const int l   = t & 31;
    const int h   = l >> 4;         // half: even/odd samples
    const int ti  = (l >> 2) & 3;   // i channels 8ti..8ti+7
    const int tj  = l & 3;          // j channels 8tj..8tj+7
    const int sl  = l & 7;          // staging slot (16B columns)
    const int s0  = l >> 3;         // staging base sample block

    unsigned char* wbase = smem_raw + w * WARP_B;
    const uint32_t wsm = (uint32_t)__cvta_generic_to_shared(wbase);

    u64 acc[8][4];
#pragma unroll
    for (int i = 0; i < 8; i++)
#pragma unroll
        for (int j = 0; j < 4; j++) acc[i][j] = 0ull;

    float msum = 0.f;                // channel sum for channel l

    const long wbase4 = (long)bid * (P1_ROWS * 8) + (long)w * (P1_WROWS * 8);
    // per-lane staging dst offset within a buffer (bytes): sample row s0+4kk, col sl
    // dst(kk) = (s0 + 4*kk)*144 + 16*sl

    // ---- preload chunks 0 and 1 ----
#pragma unroll
    for (int cc = 0; cc < 2; cc++) {
        uint32_t db = wsm + cc * BUF_B + 16 * sl;
        const float4* src = in4 + wbase4 + (long)cc * (P1_CHUNK * 8) + l;
#pragma unroll
        for (int kk = 0; kk < 4; kk++)
            cp16(db + (s0 + 4 * kk) * 144, src + 32 * kk);
        cp_commit();
    }

#pragma unroll
    for (int c = 0; c < P1_CHUNKS; c++) {
        if (c < P1_CHUNKS - 1) cp_wait<1>(); else cp_wait<0>();
        __syncwarp();
        const float* wstf = (const float*)(wbase + (c & 1) * BUF_B);
        // ---- compute: half h processes samples 2ss+h ----
#pragma unroll
        for (int ss = 0; ss < 8; ss++) {
            const float* row = wstf + (2 * ss + h) * ZR;
            float4 zia = *(const float4*)(row + 8 * ti);
            float4 zib = *(const float4*)(row + 8 * ti + 4);
            ulonglong2 zj0 = *(const ulonglong2*)(row + 8 * tj);
            ulonglong2 zj1 = *(const ulonglong2*)(row + 8 * tj + 4);
            u64 zj[4];
            zj[0] = zj0.x; zj[1] = zj0.y; zj[2] = zj1.x; zj[3] = zj1.y;
            u64 zi[8];
            zi[0] = pack2(zia.x, zia.x); zi[1] = pack2(zia.y, zia.y);
            zi[2] = pack2(zia.z, zia.z); zi[3] = pack2(zia.w, zia.w);
            zi[4] = pack2(zib.x, zib.x); zi[5] = pack2(zib.y, zib.y);
            zi[6] = pack2(zib.z, zib.z); zi[7] = pack2(zib.w, zib.w);
#pragma unroll
            for (int i = 0; i < 8; i++)
#pragma unroll
                for (int j = 0; j < 4; j++)
                    acc[i][j] = ffma2(zi[i], zj[j], acc[i][j]);
        }
        // ---- msum column pass: lane l sums channel l over 16 samples ----
#pragma unroll
        for (int s = 0; s < P1_CHUNK; s++)
            msum += wstf[s * ZR + l];
        __syncwarp();
        // ---- issue chunk c+2 into buf[c&1] ----
        if (c + 2 < P1_CHUNKS) {
            uint32_t db = wsm + (c & 1) * BUF_B + 16 * sl;
            const float4* src = in4 + wbase4 + (long)(c + 2) * (P1_CHUNK * 8) + l;
#pragma unroll
            for (int kk = 0; kk < 4; kk++)
                cp16(db + (s0 + 4 * kk) * 144, src + 32 * kk);
        }
        cp_commit();   // commit (possibly empty) group to keep wait counts aligned
    }
    __syncthreads();
    // ---- merge halves (l <-> l^16), write per-warp partials ----
#pragma unroll
    for (int i = 0; i < 8; i++)
#pragma unroll
        for (int j = 0; j < 4; j++) {
            float2 x = unpack2(acc[i][j]);
            float s0f = x.x + __shfl_xor_sync(0xffffffffu, x.x, 16);
            float s1f = x.y + __shfl_xor_sync(0xffffffffu, x.y, 16);
            if (h == 0) {
                red[w * 1024 + (8 * ti + i) * 32 + 8 * tj + 2 * j]     = s0f;
                red[w * 1024 + (8 * ti + i) * 32 + 8 * tj + 2 * j + 1] = s1f;
            }
        }
    __syncthreads();
    // ---- block reduce C (deterministic order) ----
#pragma unroll
    for (int r = 0; r < 4; r++) {
        int e = t + 256 * r;
        float s = 0.f;
#pragma unroll
        for (int ww = 0; ww < 8; ww++) s += red[ww * 1024 + e];
        gCovPart[(long)bid * 1024 + e] = s;
    }
    __syncthreads();
    // ---- block reduce channel sums (channel = lane) ----
    red[t] = msum;
    __syncthreads();
    if (t < 32) {
        float s = 0.f;
#pragma unroll
        for (int ww = 0; ww < 8; ww++) s += red[ww * 32 + t];
        gSumPart[bid * 32 + t] = s;
    }
}

// ============================================================================
// Kernel 1b: fold 2048 partials -> 256  (R9 exact)
// ============================================================================
__global__ __launch_bounds__(256) void k_red() {
    const int t = threadIdx.x;
    const int bid = blockIdx.x;
    const long base = (long)bid * RED_FOLD;

#pragma unroll
    for (int r = 0; r < 4; r++) {
        int e = t + 256 * r;
        float s = 0.f;
#pragma unroll
        for (int f = 0; f < RED_FOLD; f++) s += gCovPart[(base + f) * 1024 + e];
        gCov2[(long)bid * 1024 + e] = s;
    }
    if (t < 32) {
        float s = 0.f;
#pragma unroll
        for (int f = 0; f < RED_FOLD; f++) s += gSumPart[(base + f) * 32 + t];
        gSum2[bid * 32 + t] = s;
    }
}

// ============================================================================
// Kernel 2: final reduce, build S, normalize, Newton-Schulz (R9 exact)
// ============================================================================
__global__ __launch_bounds__(1024) void k_solve() {
    __shared__ float S[1024], B[1024], T1[1024], T2[1024];
    __shared__ float mu[32];
    __shared__ float redw[32];
    __shared__ float normsh;

    const int t = threadIdx.x;
    const int g = blockIdx.x;
    const int i = t >> 5, j = t & 31;

    float cv = 0.f;
    const float* cp = gCov2 + (long)g * RED_SLICES * 1024;
#pragma unroll 8
    for (int bb = 0; bb < RED_SLICES; bb++) cv += cp[bb * 1024 + t];
    if (t < 32) {
        float s = 0.f;
        const float* sp = gSum2 + g * RED_SLICES * 32;
#pragma unroll 8
        for (int bb = 0; bb < RED_SLICES; bb++) s += sp[bb * 32 + t];
        mu[t] = s * (1.0f / (float)ROWS_PER_GROUP);
    }
    __syncthreads();

    float sij = cv - (float)ROWS_PER_GROUP * mu[i] * mu[j] + ((i == j) ? EPSV : 0.f);

    float v = sij * sij;
#pragma unroll
    for (int o = 16; o; o >>= 1) v += __shfl_xor_sync(0xffffffffu, v, o);
    if (j == 0) redw[i] = v;
    __syncthreads();
    if (t < 32) {
        float x = redw[t];
#pragma unroll
        for (int o = 16; o; o >>= 1) x += __shfl_xor_sync(0xffffffffu, x, o);
        if (t == 0) normsh = sqrtf(x);
    }
    __syncthreads();
    const float nrm = normsh;

    S[t] = sij / nrm;
    B[t] = (i == j) ? 1.f : 0.f;
    __syncthreads();

    for (int it = 0; it < TITER; it++) {
        float s1 = 0.f;
#pragma unroll
        for (int kk = 0; kk < 32; kk++) s1 += B[i * 32 + kk] * B[kk * 32 + j];
        T1[t] = s1; __syncthreads();
        float s2 = 0.f;
#pragma unroll
        for (int kk = 0; kk < 32; kk++) s2 += T1[i * 32 + kk] * B[kk * 32 + j];
        T2[t] = s2; __syncthreads();
        float s3 = 0.f;
#pragma unroll
        for (int kk = 0; kk < 32; kk++) s3 += T2[i * 32 + kk] * S[kk * 32 + j];
        float nb = 1.5f * B[t] - 0.5f * s3;
        __syncthreads();
        B[t] = nb;
        __syncthreads();
    }

    const float inv = rsqrtf(nrm);
    float mt = B[j * 32 + i] * inv;
    gMt[g * 1024 + t] = mt;
    T1[t] = mt;
    __syncthreads();
    if (t < 32) {
        float bsum = 0.f;
#pragma unroll
        for (int d = 0; d < 32; d++) bsum += mu[d] * T1[d * 32 + t];
        gBias[g * 32 + t] = -bsum;
    }
}

// ============================================================================
// Kernel 3: out[n] = z[n] @ Mt + bias. R9 exact (measured 103.5us).
// ============================================================================
__global__ __launch_bounds__(P2_TPB, 3) void k2_apply(const float4* __restrict__ in4,
                                                      float4* __restrict__ out4) {
    __shared__ __align__(16) float zbuf[P2_ROWS * ZST];  // 34816 B
    __shared__ __align__(16) u64 mt2[512];
    __shared__ u64 bias2[16];

    const int t = threadIdx.x;
    const int g = blockIdx.x >> 10;          // 1024 blocks per group

    const u64* mtg = (const u64*)gMt + g * 512;
#pragma unroll
    for (int i = 0; i < 4; i++) mt2[t + 128 * i] = mtg[t + 128 * i];
    if (t < 16) bias2[t] = ((const u64*)gBias)[g * 16 + t];

    const int m = t & 3;
    const int q = t >> 2;                    // 0..31
    const long R0 = (long)blockIdx.x * P2_ROWS;

    // ---- stage 256 rows: coalesced LDG.128, float2 smem stores ----
#pragma unroll
    for (int i = 0; i < 16; i++) {
        int f = t + 128 * i;                 // float4 id in tile
        int row = f >> 3, sl = f & 7;
        float4 v = in4[R0 * 8 + f];
        float2* d = (float2*)(zbuf + row * ZST + 4 * sl);
        d[0] = make_float2(v.x, v.y);
        d[1] = make_float2(v.z, v.w);
    }
    __syncthreads();

    u64 acc[8][4];
#pragma unroll
    for (int rr = 0; rr < 8; rr++)
#pragma unroll
        for (int jj = 0; jj < 4; jj++) acc[rr][jj] = bias2[m * 4 + jj];

    const ulonglong2* mtv = (const ulonglong2*)mt2;
#pragma unroll 4
    for (int dp = 0; dp < 16; dp++) {
        const int d0 = 2 * dp;
        ulonglong2 ma0 = mtv[d0 * 8 + m * 2 + 0];
        ulonglong2 mb0 = mtv[d0 * 8 + m * 2 + 1];
        ulonglong2 ma1 = mtv[d0 * 8 + m * 2 + 8];   // (d0+1)
        ulonglong2 mb1 = mtv[d0 * 8 + m * 2 + 9];
#pragma unroll
        for (int rr = 0; rr < 8; rr++) {
            float2 z2 = *(const float2*)(zbuf + (q + 32 * rr) * ZST + d0);
            u64 zz0 = pack2(z2.x, z2.x);
            u64 zz1 = pack2(z2.y, z2.y);
            acc[rr][0] = ffma2(zz0, ma0.x, acc[rr][0]);
            acc[rr][1] = ffma2(zz0, ma0.y, acc[rr][1]);
            acc[rr][2] = ffma2(zz0, mb0.x, acc[rr][2]);
            acc[rr][3] = ffma2(zz0, mb0.y, acc[rr][3]);
            acc[rr][0] = ffma2(zz1, ma1.x, acc[rr][0]);
            acc[rr][1] = ffma2(zz1, ma1.y, acc[rr][1]);
            acc[rr][2] = ffma2(zz1, mb1.x, acc[rr][2]);
            acc[rr][3] = ffma2(zz1, mb1.y, acc[rr][3]);
        }
    }

#pragma unroll
    for (int rr = 0; rr < 8; rr++) {
        float2 p0 = unpack2(acc[rr][0]), p1 = unpack2(acc[rr][1]);
        float2 p2 = unpack2(acc[rr][2]), p3 = unpack2(acc[rr][3]);
        long rowb = (R0 + q + 32 * rr) * 8;
        out4[rowb + m * 2 + 0] = make_float4(p0.x, p0.y, p1.x, p1.y);
        out4[rowb + m * 2 + 1] = make_float4(p2.x, p2.y, p3.x, p3.y);
    }
}

// ============================================================================
extern "C" void kernel_launch(void* const* d_in, const int* in_sizes, int n_in,
                              void* d_out, int out_size) {
    const float4* in4 = (const float4*)d_in[0];
    float4* out4 = (float4*)d_out;

    k1_stats<<<P1_GRID, 256>>>(in4);
    k_red<<<GROUPS * RED_SLICES, 256>>>();
    k_solve<<<GROUPS, 1024>>>();
    k2_apply<<<P2_GRID, P2_TPB>>>(in4, out4);
}